// round 14
// baseline (speedup 1.0000x reference)
#include <cuda_runtime.h>
#include <cuda_fp16.h>
#include <math.h>
#include <stdint.h>

#define NN   50000
#define EE   400000
#define FIN  128
#define HID  64
#define HEADS 4
#define NCLS 121
#define M1   256
#define M3   484
#define NPAD 50048
#define P1   520   // L1 fp32 out pitch: [xh(256) | lin(256) | as(4) | ad(4)]
#define P2   264   // L2 fp32 out pitch: [xh(256) | as(4) | ad(4)]
#define P3   616   // L3 fp32 out pitch: [xh(484) | lin(121) | as(4) | ad(4)]
// Bt regions (halves)
#define BT_L1 0
#define BT_L2 66560    // 520*128
#define BT_L3 134144   // +264*256

// ---------------- scratch ----------------
__device__ float  g_xh [(size_t)NN * P3];
__device__ float  g_h  [(size_t)NN * M1];
__device__ float  g_wext[3 * 256 * 8];
__device__ __half g_Ah[(size_t)NPAD * 512];
__device__ __half g_Bt[(size_t)640 * 512];
__device__ int    g_deg   [NN];
__device__ int    g_rowptr[NN + 1];
__device__ int    g_cursor[NN];
__device__ int    g_csrsrc[EE];
__device__ float  g_alpha [(size_t)EE * HEADS];

// ---------------- conversions ----------------
__global__ void convA(const float* __restrict__ X, __half* __restrict__ Ap, int Nrows, int K) {
    long i = blockIdx.x * (long)blockDim.x + threadIdx.x;
    long tot = (long)Nrows * K;
    long stride = (long)gridDim.x * blockDim.x;
    for (; i < tot; i += stride)
        Ap[i] = __float2half_rn(X[i]);
}
// all three layers' alpha-projection columns in one launch
__global__ void wext_all(const float* __restrict__ W1, const float* __restrict__ a1s, const float* __restrict__ a1d,
                         const float* __restrict__ W2, const float* __restrict__ a2s, const float* __restrict__ a2d,
                         const float* __restrict__ W3, const float* __restrict__ a3s, const float* __restrict__ a3d,
                         float* __restrict__ wext) {
    int t = blockIdx.x * blockDim.x + threadIdx.x;   // (128+256+256)*8 = 5120
    if (t >= 5120) return;
    const float *W, *avs, *avd; float* wo; int k, ldw, C;
    if (t < 1024)       { W = W1; avs = a1s; avd = a1d; wo = wext;            k = t >> 3; ldw = 256; C = HID; }
    else if (t < 3072)  { int u = t - 1024; W = W2; avs = a2s; avd = a2d; wo = wext + 2048; k = u >> 3; ldw = 256; C = HID; }
    else                { int u = t - 3072; W = W3; avs = a3s; avd = a3d; wo = wext + 4096; k = u >> 3; ldw = M3;  C = NCLS; }
    int j = t & 7, h = j & 3;
    const float* av = ((j >= 4) ? avd : avs) + h * C;
    const float* wr = W + (size_t)k * ldw + h * C;
    float s = 0.f;
    for (int c = 0; c < C; c++) s += wr[c] * av[c];
    wo[k * 8 + j] = s;
}
__global__ void convB_L1(const float* __restrict__ W1, const float* __restrict__ linW,
                         const float* __restrict__ wext, __half* __restrict__ Bp) {
    int i = blockIdx.x * blockDim.x + threadIdx.x;
    if (i >= 520 * 128) return;
    int n = i >> 7, k = i & 127;
    float w;
    if (n < 256)      w = W1[(size_t)k * 256 + n];
    else if (n < 512) w = linW[(size_t)k * 256 + (n - 256)];
    else              w = wext[k * 8 + (n - 512)];
    Bp[(size_t)n * 128 + k] = __float2half_rn(w);
}
__global__ void convB_W2(const float* __restrict__ W, const float* __restrict__ wext,
                         __half* __restrict__ Bp) {
    int i = blockIdx.x * blockDim.x + threadIdx.x;
    if (i >= 264 * 256) return;
    int n = i >> 8, k = i & 255;
    float w = (n < 256) ? W[(size_t)k * 256 + n] : wext[k * 8 + (n - 256)];
    Bp[(size_t)n * 256 + k] = __float2half_rn(w);
}
__global__ void convB_L3(const float* __restrict__ W3, const float* __restrict__ linW,
                         const float* __restrict__ wext, __half* __restrict__ Bp) {
    int i = blockIdx.x * blockDim.x + threadIdx.x;
    if (i >= 640 * 256) return;
    int n = i >> 8, k = i & 255;
    float w = 0.f;
    if (n < 484)      w = W3[(size_t)k * M3 + n];
    else if (n < 605) w = linW[(size_t)k * NCLS + (n - 484)];
    else if (n < 613) w = wext[k * 8 + (n - 605)];
    Bp[(size_t)n * 256 + k] = __float2half_rn(w);
}

// ---------------- pipelined HMMA fp16 GEMM (unchanged) ----------------
#define PITCH 80
#define STAGE_BYTES (128 * PITCH)
__global__ __launch_bounds__(256) void gemm_mma(const __half* __restrict__ A,
                                                const __half* __restrict__ Bt,
                                                float* __restrict__ C,
                                                int Nrows, int Kp, int Nout, int ldc) {
    __shared__ __align__(16) uint8_t smem[4 * STAGE_BYTES];
    uint32_t sbase = (uint32_t)__cvta_generic_to_shared(smem);
    int tid  = threadIdx.x;
    int wid  = tid >> 5, lane = tid & 31;
    int wm   = wid & 1, wn = wid >> 1;
    int g    = lane >> 2, tg = lane & 3;
    int rowBase = blockIdx.y * 128;
    int colBase = blockIdx.x * 128;
    int lrow = (lane & 7) + ((lane >> 3) & 1) * 8;
    int lcol = (lane >> 4) * 16;

    float acc[4][4][4];
#pragma unroll
    for (int i = 0; i < 4; i++)
#pragma unroll
        for (int j = 0; j < 4; j++)
#pragma unroll
            for (int q = 0; q < 4; q++) acc[i][j][q] = 0.f;

    int isB = tid >> 7;
    int lr  = tid & 127;
    const __half* gsrc = isB ? (Bt + (size_t)(colBase + lr) * Kp)
                             : (A  + (size_t)(rowBase + lr) * Kp);
    int niter = Kp >> 5;
    {
        uint32_t dst = sbase + (uint32_t)isB * STAGE_BYTES + lr * PITCH;
        const uint8_t* src = (const uint8_t*)(gsrc);
#pragma unroll
        for (int c = 0; c < 4; c++)
            asm volatile("cp.async.cg.shared.global [%0], [%1], 16;"
                         :: "r"(dst + c * 16), "l"(src + c * 16) : "memory");
        asm volatile("cp.async.commit_group;" ::: "memory");
    }
    for (int it = 0; it < niter; it++) {
        if (it + 1 < niter) {
            uint32_t dst = sbase + ((it + 1) & 1) * 2 * STAGE_BYTES + (uint32_t)isB * STAGE_BYTES + lr * PITCH;
            const uint8_t* src = (const uint8_t*)(gsrc + (it + 1) * 32);
#pragma unroll
            for (int c = 0; c < 4; c++)
                asm volatile("cp.async.cg.shared.global [%0], [%1], 16;"
                             :: "r"(dst + c * 16), "l"(src + c * 16) : "memory");
            asm volatile("cp.async.commit_group;" ::: "memory");
            asm volatile("cp.async.wait_group 1;" ::: "memory");
        } else {
            asm volatile("cp.async.wait_group 0;" ::: "memory");
        }
        __syncthreads();
        uint32_t sA = sbase + (it & 1) * 2 * STAGE_BYTES;
        uint32_t sB = sA + STAGE_BYTES;
#pragma unroll
        for (int ks = 0; ks < 2; ks++) {
            int kbyte = ks * 32;
            uint32_t a[4][4], b[2][4];
#pragma unroll
            for (int i = 0; i < 4; i++) {
                uint32_t addr = sA + (wm * 64 + i * 16 + lrow) * PITCH + kbyte + lcol;
                asm volatile("ldmatrix.sync.aligned.m8n8.x4.shared.b16 {%0,%1,%2,%3}, [%4];"
                             : "=r"(a[i][0]), "=r"(a[i][1]), "=r"(a[i][2]), "=r"(a[i][3]) : "r"(addr));
            }
#pragma unroll
            for (int p = 0; p < 2; p++) {
                uint32_t addr = sB + (wn * 32 + p * 16 + lrow) * PITCH + kbyte + lcol;
                asm volatile("ldmatrix.sync.aligned.m8n8.x4.shared.b16 {%0,%1,%2,%3}, [%4];"
                             : "=r"(b[p][0]), "=r"(b[p][1]), "=r"(b[p][2]), "=r"(b[p][3]) : "r"(addr));
            }
#pragma unroll
            for (int i = 0; i < 4; i++)
#pragma unroll
                for (int j = 0; j < 4; j++) {
                    uint32_t b0 = b[j >> 1][j & 1];
                    uint32_t b1 = b[j >> 1][2 + (j & 1)];
                    asm volatile(
                        "mma.sync.aligned.m16n8k16.row.col.f32.f16.f16.f32 "
                        "{%0,%1,%2,%3}, {%4,%5,%6,%7}, {%8,%9}, {%0,%1,%2,%3};"
                        : "+f"(acc[i][j][0]), "+f"(acc[i][j][1]), "+f"(acc[i][j][2]), "+f"(acc[i][j][3])
                        : "r"(a[i][0]), "r"(a[i][1]), "r"(a[i][2]), "r"(a[i][3]),
                          "r"(b0), "r"(b1));
                }
        }
        __syncthreads();
    }
#pragma unroll
    for (int i = 0; i < 4; i++) {
        int r0 = rowBase + wm * 64 + i * 16 + g;
#pragma unroll
        for (int j = 0; j < 4; j++) {
            int c0 = colBase + wn * 32 + j * 8 + tg * 2;
            if (r0 < Nrows) {
                if (c0     < Nout) C[(size_t)r0 * ldc + c0]     = acc[i][j][0];
                if (c0 + 1 < Nout) C[(size_t)r0 * ldc + c0 + 1] = acc[i][j][1];
            }
            if (r0 + 8 < Nrows) {
                if (c0     < Nout) C[(size_t)(r0 + 8) * ldc + c0]     = acc[i][j][2];
                if (c0 + 1 < Nout) C[(size_t)(r0 + 8) * ldc + c0 + 1] = acc[i][j][3];
            }
        }
    }
}

// ---------------- CSR construction ----------------
__global__ void zero_i(int* p, int n) {
    int i = blockIdx.x * blockDim.x + threadIdx.x;
    if (i < n) p[i] = 0;
}
__global__ void hist_dst(const int* __restrict__ ei, int* __restrict__ deg) {
    int e = blockIdx.x * blockDim.x + threadIdx.x;
    if (e < EE) atomicAdd(&deg[ei[EE + e]], 1);
}
__global__ void scan_deg(const int* __restrict__ deg, int* __restrict__ rowptr, int* __restrict__ cursor) {
    __shared__ int part[512];
    int t = threadIdx.x;
    const int CH = (NN + 511) / 512;
    int start = t * CH;
    int s = 0;
    for (int i = 0; i < CH; i++) {
        int idx = start + i;
        if (idx < NN) s += deg[idx];
    }
    part[t] = s;
    __syncthreads();
    for (int off = 1; off < 512; off <<= 1) {
        int v = (t >= off) ? part[t - off] : 0;
        __syncthreads();
        part[t] += v;
        __syncthreads();
    }
    int base = (t == 0) ? 0 : part[t - 1];
    for (int i = 0; i < CH; i++) {
        int idx = start + i;
        if (idx < NN) {
            rowptr[idx] = base;
            cursor[idx] = base;
            base += deg[idx];
        }
    }
    if (t == 511) rowptr[NN] = part[511];
}
__global__ void scatter_csr(const int* __restrict__ ei, int* __restrict__ cursor,
                            int* __restrict__ csrsrc) {
    int e = blockIdx.x * blockDim.x + threadIdx.x;
    if (e >= EE) return;
    int dst = ei[EE + e];
    int p = atomicAdd(&cursor[dst], 1);
    csrsrc[p] = ei[e];
}

// ---------------- fused softmax (warp 0) helper ----------------
// computes normalized alpha for node n's CSR range into global alpha buffer.
// layout: lane = h(4) x slot(8). AS/AD are columns of xh at given pitch.
__device__ __forceinline__ void node_softmax(int beg, int end, int lane,
                                             const float* __restrict__ AS,
                                             const float* __restrict__ AD,
                                             int pitch, size_t nrow,
                                             const int* __restrict__ csrsrc,
                                             float* __restrict__ alpha) {
    int h  = lane >> 3;
    int j0 = lane & 7;
    float adv = AD[nrow * pitch + h];
    float m = -INFINITY, den = 0.f;
    for (int i = beg + j0; i < end; i += 8) {
        float lg = AS[(size_t)csrsrc[i] * pitch + h] + adv;
        lg = lg > 0.f ? lg : 0.2f * lg;
        alpha[(size_t)i * HEADS + h] = lg;
        if (lg > m) { den = den * expf(m - lg) + 1.f; m = lg; }
        else        { den += expf(lg - m); }
    }
#pragma unroll
    for (int o = 1; o < 8; o <<= 1) {
        float mo = __shfl_xor_sync(0xffffffffu, m, o);
        float dn = __shfl_xor_sync(0xffffffffu, den, o);
        float mn = fmaxf(m, mo);
        float f1 = (m  == mn) ? 1.f : expf(m - mn);
        float f2 = (mo == mn) ? 1.f : expf(mo - mn);
        den = den * f1 + dn * f2;
        m = mn;
    }
    float inv = 1.f / (den + 1e-16f);
    for (int i = beg + j0; i < end; i += 8)
        alpha[(size_t)i * HEADS + h] = expf(alpha[(size_t)i * HEADS + h] - m) * inv;
}

// ---------------- float4 aggregation core ----------------
__device__ __forceinline__ float4 agg_acc4(int beg, int end,
                                           const int* __restrict__ csrsrc,
                                           const float* __restrict__ alpha,
                                           const float* __restrict__ xh,
                                           int pitch, int cb, int h) {
    float4 acc = make_float4(0.f, 0.f, 0.f, 0.f);
    int i = beg;
    for (; i + 7 < end; i += 8) {
        int s[8]; float a[8]; float4 x[8];
#pragma unroll
        for (int u = 0; u < 8; u++) s[u] = csrsrc[i + u];
#pragma unroll
        for (int u = 0; u < 8; u++) a[u] = alpha[(size_t)(i + u) * HEADS + h];
#pragma unroll
        for (int u = 0; u < 8; u++) x[u] = *(const float4*)(xh + (size_t)s[u] * pitch + cb);
#pragma unroll
        for (int u = 0; u < 8; u++) {
            acc.x += a[u] * x[u].x; acc.y += a[u] * x[u].y;
            acc.z += a[u] * x[u].z; acc.w += a[u] * x[u].w;
        }
    }
    for (; i + 3 < end; i += 4) {
        int s0 = csrsrc[i], s1 = csrsrc[i + 1], s2 = csrsrc[i + 2], s3 = csrsrc[i + 3];
        float a0 = alpha[(size_t)i * HEADS + h];
        float a1 = alpha[(size_t)(i + 1) * HEADS + h];
        float a2 = alpha[(size_t)(i + 2) * HEADS + h];
        float a3 = alpha[(size_t)(i + 3) * HEADS + h];
        float4 x0 = *(const float4*)(xh + (size_t)s0 * pitch + cb);
        float4 x1 = *(const float4*)(xh + (size_t)s1 * pitch + cb);
        float4 x2 = *(const float4*)(xh + (size_t)s2 * pitch + cb);
        float4 x3 = *(const float4*)(xh + (size_t)s3 * pitch + cb);
        acc.x += a0 * x0.x + a1 * x1.x + a2 * x2.x + a3 * x3.x;
        acc.y += a0 * x0.y + a1 * x1.y + a2 * x2.y + a3 * x3.y;
        acc.z += a0 * x0.z + a1 * x1.z + a2 * x2.z + a3 * x3.z;
        acc.w += a0 * x0.w + a1 * x1.w + a2 * x2.w + a3 * x3.w;
    }
    for (; i < end; i++) {
        float a = alpha[(size_t)i * HEADS + h];
        float4 x = *(const float4*)(xh + (size_t)csrsrc[i] * pitch + cb);
        acc.x += a * x.x; acc.y += a * x.y; acc.z += a * x.z; acc.w += a * x.w;
    }
    return acc;
}
__device__ __forceinline__ float4 agg_acc4_mh(int beg, int end,
                                              const int* __restrict__ csrsrc,
                                              const float* __restrict__ alpha,
                                              const float* __restrict__ xh,
                                              int pitch, int cb,
                                              int h0, int h1, int h2, int h3) {
    float4 acc = make_float4(0.f, 0.f, 0.f, 0.f);
    for (int i = beg; i < end; i++) {
        float4 av = *(const float4*)(alpha + (size_t)i * HEADS);
        const float* ap = (const float*)&av;
        float4 x = *(const float4*)(xh + (size_t)csrsrc[i] * pitch + cb);
        acc.x += ap[h0] * x.x; acc.y += ap[h1] * x.y;
        acc.z += ap[h2] * x.z; acc.w += ap[h3] * x.w;
    }
    return acc;
}

// ---------------- fused GAT layer kernels: softmax(warp0) + agg + finalize ----------------
__global__ __launch_bounds__(64) void gat1(
        const int* __restrict__ rowptr, const int* __restrict__ csrsrc,
        float* __restrict__ alpha, const float* __restrict__ xh,
        const float* __restrict__ b1, const float* __restrict__ lin1b,
        float* __restrict__ h_out, __half* __restrict__ Ap) {
    int n = blockIdx.x;
    int beg = rowptr[n], end = rowptr[n + 1];
    if (threadIdx.x < 32)
        node_softmax(beg, end, threadIdx.x, xh + 512, xh + 516, P1, n, csrsrc, alpha);
    __syncthreads();
    int cb = threadIdx.x * 4;
    float4 acc = agg_acc4(beg, end, csrsrc, alpha, xh, P1, cb, cb >> 6);
    float4 skip = *(const float4*)(xh + (size_t)n * P1 + 256 + cb);
    float4 bb   = *(const float4*)(b1 + cb);
    float4 lb   = *(const float4*)(lin1b + cb);
    float v[4] = { acc.x + bb.x + skip.x + lb.x, acc.y + bb.y + skip.y + lb.y,
                   acc.z + bb.z + skip.z + lb.z, acc.w + bb.w + skip.w + lb.w };
    __half* row = Ap + (size_t)n * 256;
    float* ho = h_out + (size_t)n * M1 + cb;
#pragma unroll
    for (int u = 0; u < 4; u++) {
        float t = v[u] > 0.f ? v[u] : expm1f(v[u]);
        ho[u] = t;
        row[cb + u] = __float2half_rn(t);
    }
}

__global__ __launch_bounds__(64) void gat2(
        const int* __restrict__ rowptr, const int* __restrict__ csrsrc,
        float* __restrict__ alpha, const float* __restrict__ xh,
        const float* __restrict__ b2,
        float* __restrict__ h_io, __half* __restrict__ Ap) {
    int n = blockIdx.x;
    int beg = rowptr[n], end = rowptr[n + 1];
    if (threadIdx.x < 32)
        node_softmax(beg, end, threadIdx.x, xh + 256, xh + 260, P2, n, csrsrc, alpha);
    __syncthreads();
    int cb = threadIdx.x * 4;
    float4 acc = agg_acc4(beg, end, csrsrc, alpha, xh, P2, cb, cb >> 6);
    float4 bb = *(const float4*)(b2 + cb);
    float* hp = h_io + (size_t)n * M1 + cb;
    float4 hv = *(const float4*)hp;
    float v[4] = { acc.x + bb.x + hv.x, acc.y + bb.y + hv.y,
                   acc.z + bb.z + hv.z, acc.w + bb.w + hv.w };
    __half* row = Ap + (size_t)n * 256;
#pragma unroll
    for (int u = 0; u < 4; u++) {
        float t = v[u] > 0.f ? v[u] : expm1f(v[u]);
        hp[u] = t;
        row[cb + u] = __float2half_rn(t);
    }
}

__global__ __launch_bounds__(128) void gat3(
        const int* __restrict__ rowptr, const int* __restrict__ csrsrc,
        float* __restrict__ alpha, const float* __restrict__ xh,
        const float* __restrict__ b3, const float* __restrict__ lin3b,
        float* __restrict__ out) {
    __shared__ float sm[M3];
    int n = blockIdx.x;
    int beg = rowptr[n], end = rowptr[n + 1];
    if (threadIdx.x < 32)
        node_softmax(beg, end, threadIdx.x, xh + 605, xh + 609, P3, n, csrsrc, alpha);
    __syncthreads();
    int c4 = threadIdx.x;
    if (c4 < 121) {
        int cb = c4 * 4;
        int h0 = cb / NCLS, h1 = (cb + 1) / NCLS, h2 = (cb + 2) / NCLS, h3 = (cb + 3) / NCLS;
        float4 acc;
        if (h0 == h3) acc = agg_acc4(beg, end, csrsrc, alpha, xh, P3, cb, h0);
        else          acc = agg_acc4_mh(beg, end, csrsrc, alpha, xh, P3, cb, h0, h1, h2, h3);
        sm[cb] = acc.x; sm[cb + 1] = acc.y; sm[cb + 2] = acc.z; sm[cb + 3] = acc.w;
    }
    __syncthreads();
    int c = threadIdx.x;
    if (c < NCLS) {
        float s = 0.25f * (sm[c] + sm[NCLS + c] + sm[2 * NCLS + c] + sm[3 * NCLS + c]);
        out[(size_t)n * NCLS + c] = s + b3[c] + xh[(size_t)n * P3 + 484 + c] + lin3b[c];
    }
}

// ---------------- host ----------------
static void launch_gemm(const __half* Ap, const __half* Bp, float* C,
                        int Nrows, int Kp, int Nout, int ldc) {
    dim3 gg((Nout + 127) / 128, (Nrows + 127) / 128);
    gemm_mma<<<gg, 256>>>(Ap, Bp, C, Nrows, Kp, Nout, ldc);
}

extern "C" void kernel_launch(void* const* d_in, const int* in_sizes, int n_in,
                              void* d_out, int out_size) {
    const float* x      = (const float*)d_in[0];
    const int*   ei     = (const int*)  d_in[1];
    const float* W1     = (const float*)d_in[2];
    const float* a1s    = (const float*)d_in[3];
    const float* a1d    = (const float*)d_in[4];
    const float* b1     = (const float*)d_in[5];
    const float* lin1W  = (const float*)d_in[6];
    const float* lin1b  = (const float*)d_in[7];
    const float* W2     = (const float*)d_in[8];
    const float* a2s    = (const float*)d_in[9];
    const float* a2d    = (const float*)d_in[10];
    const float* b2     = (const float*)d_in[11];
    const float* W3     = (const float*)d_in[12];
    const float* a3s    = (const float*)d_in[13];
    const float* a3d    = (const float*)d_in[14];
    const float* b3     = (const float*)d_in[15];
    const float* lin3W  = (const float*)d_in[16];
    const float* lin3b  = (const float*)d_in[17];
    float* out = (float*)d_out;

    float *xh, *h, *alpha, *wext;
    __half *Ah, *Bt;
    int *deg, *rowptr, *cursor, *csrsrc;
    cudaGetSymbolAddress((void**)&xh,  g_xh);
    cudaGetSymbolAddress((void**)&h,   g_h);
    cudaGetSymbolAddress((void**)&alpha, g_alpha);
    cudaGetSymbolAddress((void**)&wext, g_wext);
    cudaGetSymbolAddress((void**)&Ah,  g_Ah);
    cudaGetSymbolAddress((void**)&Bt,  g_Bt);
    cudaGetSymbolAddress((void**)&deg,    g_deg);
    cudaGetSymbolAddress((void**)&rowptr, g_rowptr);
    cudaGetSymbolAddress((void**)&cursor, g_cursor);
    cudaGetSymbolAddress((void**)&csrsrc, g_csrsrc);

    // ---- all weight prep + input conversion up front ----
    convA<<<2048, 256>>>(x, Ah, NN, FIN);
    wext_all<<<(5120 + 255) / 256, 256>>>(W1, a1s, a1d, W2, a2s, a2d, W3, a3s, a3d, wext);
    convB_L1<<<(520 * 128 + 255) / 256, 256>>>(W1, lin1W, wext, Bt + BT_L1);
    convB_W2<<<(264 * 256 + 255) / 256, 256>>>(W2, wext + 2048, Bt + BT_L2);
    convB_L3<<<(640 * 256 + 255) / 256, 256>>>(W3, lin3W, wext + 4096, Bt + BT_L3);

    // ---- CSR build ----
    zero_i<<<(NN + 255) / 256, 256>>>(deg, NN);
    hist_dst<<<(EE + 255) / 256, 256>>>(ei, deg);
    scan_deg<<<1, 512>>>(deg, rowptr, cursor);
    scatter_csr<<<(EE + 255) / 256, 256>>>(ei, cursor, csrsrc);

    // ---- layer 1 ----
    launch_gemm(Ah, Bt + BT_L1, xh, NN, 128, 520, P1);
    gat1<<<NN, 64>>>(rowptr, csrsrc, alpha, xh, b1, lin1b, h, Ah);

    // ---- layer 2 ----
    launch_gemm(Ah, Bt + BT_L2, xh, NN, 256, 264, P2);
    gat2<<<NN, 64>>>(rowptr, csrsrc, alpha, xh, b2, h, Ah);

    // ---- layer 3 ----
    launch_gemm(Ah, Bt + BT_L3, xh, NN, 256, 613, P3);
    gat3<<<NN, 128>>>(rowptr, csrsrc, alpha, xh, b3, lin3b, out);

    (void)in_sizes; (void)n_in; (void)out_size;
}

// round 15
// speedup vs baseline: 1.0467x; 1.0467x over previous
#include <cuda_runtime.h>
#include <cuda_fp16.h>
#include <math.h>
#include <stdint.h>

#define NN   50000
#define EE   400000
#define FIN  128
#define HID  64
#define HEADS 4
#define NCLS 121
#define M1   256
#define M3   484
#define NPAD 50048
#define P1   520   // L1 fp32 out pitch: [xh(256) | lin(256) | as(4) | ad(4)]
#define P2   264   // L2 fp32 out pitch: [xh(256) | as(4) | ad(4)]
#define P3   616   // L3 fp32 out pitch: [xh(484) | lin(121) | as(4) | ad(4)]
// Bt regions (halves)
#define BT_L1 0
#define BT_L2 66560    // 520*128
#define BT_L3 134144   // +264*256

// ---------------- scratch ----------------
__device__ float  g_xh [(size_t)NN * P3];
__device__ float  g_h  [(size_t)NN * M1];
__device__ float  g_wext[3 * 256 * 8];
__device__ __half g_Ah[(size_t)NPAD * 512];
__device__ __half g_Bt[(size_t)640 * 512];
__device__ int    g_deg   [NN];
__device__ int    g_rowptr[NN + 1];
__device__ int    g_cursor[NN];
__device__ int    g_csrsrc[EE];
__device__ float  g_alpha [(size_t)EE * HEADS];

// ---------------- conversions ----------------
__global__ void convA(const float* __restrict__ X, __half* __restrict__ Ap, int Nrows, int K) {
    long i = blockIdx.x * (long)blockDim.x + threadIdx.x;
    long tot = (long)Nrows * K;
    long stride = (long)gridDim.x * blockDim.x;
    for (; i < tot; i += stride)
        Ap[i] = __float2half_rn(X[i]);
}
__global__ void wext_all(const float* __restrict__ W1, const float* __restrict__ a1s, const float* __restrict__ a1d,
                         const float* __restrict__ W2, const float* __restrict__ a2s, const float* __restrict__ a2d,
                         const float* __restrict__ W3, const float* __restrict__ a3s, const float* __restrict__ a3d,
                         float* __restrict__ wext) {
    int t = blockIdx.x * blockDim.x + threadIdx.x;   // (128+256+256)*8 = 5120
    if (t >= 5120) return;
    const float *W, *avs, *avd; float* wo; int k, ldw, C;
    if (t < 1024)       { W = W1; avs = a1s; avd = a1d; wo = wext;            k = t >> 3; ldw = 256; C = HID; }
    else if (t < 3072)  { int u = t - 1024; W = W2; avs = a2s; avd = a2d; wo = wext + 2048; k = u >> 3; ldw = 256; C = HID; }
    else                { int u = t - 3072; W = W3; avs = a3s; avd = a3d; wo = wext + 4096; k = u >> 3; ldw = M3;  C = NCLS; }
    int j = t & 7, h = j & 3;
    const float* av = ((j >= 4) ? avd : avs) + h * C;
    const float* wr = W + (size_t)k * ldw + h * C;
    float s = 0.f;
    for (int c = 0; c < C; c++) s += wr[c] * av[c];
    wo[k * 8 + j] = s;
}
__global__ void convB_L1(const float* __restrict__ W1, const float* __restrict__ linW,
                         const float* __restrict__ wext, __half* __restrict__ Bp) {
    int i = blockIdx.x * blockDim.x + threadIdx.x;
    if (i >= 520 * 128) return;
    int n = i >> 7, k = i & 127;
    float w;
    if (n < 256)      w = W1[(size_t)k * 256 + n];
    else if (n < 512) w = linW[(size_t)k * 256 + (n - 256)];
    else              w = wext[k * 8 + (n - 512)];
    Bp[(size_t)n * 128 + k] = __float2half_rn(w);
}
__global__ void convB_W2(const float* __restrict__ W, const float* __restrict__ wext,
                         __half* __restrict__ Bp) {
    int i = blockIdx.x * blockDim.x + threadIdx.x;
    if (i >= 264 * 256) return;
    int n = i >> 8, k = i & 255;
    float w = (n < 256) ? W[(size_t)k * 256 + n] : wext[k * 8 + (n - 256)];
    Bp[(size_t)n * 256 + k] = __float2half_rn(w);
}
__global__ void convB_L3(const float* __restrict__ W3, const float* __restrict__ linW,
                         const float* __restrict__ wext, __half* __restrict__ Bp) {
    int i = blockIdx.x * blockDim.x + threadIdx.x;
    if (i >= 640 * 256) return;
    int n = i >> 8, k = i & 255;
    float w = 0.f;
    if (n < 484)      w = W3[(size_t)k * M3 + n];
    else if (n < 605) w = linW[(size_t)k * NCLS + (n - 484)];
    else if (n < 613) w = wext[k * 8 + (n - 605)];
    Bp[(size_t)n * 256 + k] = __float2half_rn(w);
}

// ---------------- pipelined HMMA fp16 GEMM ----------------
#define PITCH 80
#define STAGE_BYTES (128 * PITCH)
__global__ __launch_bounds__(256) void gemm_mma(const __half* __restrict__ A,
                                                const __half* __restrict__ Bt,
                                                float* __restrict__ C,
                                                int Nrows, int Kp, int Nout, int ldc) {
    __shared__ __align__(16) uint8_t smem[4 * STAGE_BYTES];
    uint32_t sbase = (uint32_t)__cvta_generic_to_shared(smem);
    int tid  = threadIdx.x;
    int wid  = tid >> 5, lane = tid & 31;
    int wm   = wid & 1, wn = wid >> 1;
    int g    = lane >> 2, tg = lane & 3;
    int rowBase = blockIdx.y * 128;
    int colBase = blockIdx.x * 128;
    int lrow = (lane & 7) + ((lane >> 3) & 1) * 8;
    int lcol = (lane >> 4) * 16;

    float acc[4][4][4];
#pragma unroll
    for (int i = 0; i < 4; i++)
#pragma unroll
        for (int j = 0; j < 4; j++)
#pragma unroll
            for (int q = 0; q < 4; q++) acc[i][j][q] = 0.f;

    int isB = tid >> 7;
    int lr  = tid & 127;
    const __half* gsrc = isB ? (Bt + (size_t)(colBase + lr) * Kp)
                             : (A  + (size_t)(rowBase + lr) * Kp);
    int niter = Kp >> 5;
    {
        uint32_t dst = sbase + (uint32_t)isB * STAGE_BYTES + lr * PITCH;
        const uint8_t* src = (const uint8_t*)(gsrc);
#pragma unroll
        for (int c = 0; c < 4; c++)
            asm volatile("cp.async.cg.shared.global [%0], [%1], 16;"
                         :: "r"(dst + c * 16), "l"(src + c * 16) : "memory");
        asm volatile("cp.async.commit_group;" ::: "memory");
    }
    for (int it = 0; it < niter; it++) {
        if (it + 1 < niter) {
            uint32_t dst = sbase + ((it + 1) & 1) * 2 * STAGE_BYTES + (uint32_t)isB * STAGE_BYTES + lr * PITCH;
            const uint8_t* src = (const uint8_t*)(gsrc + (it + 1) * 32);
#pragma unroll
            for (int c = 0; c < 4; c++)
                asm volatile("cp.async.cg.shared.global [%0], [%1], 16;"
                             :: "r"(dst + c * 16), "l"(src + c * 16) : "memory");
            asm volatile("cp.async.commit_group;" ::: "memory");
            asm volatile("cp.async.wait_group 1;" ::: "memory");
        } else {
            asm volatile("cp.async.wait_group 0;" ::: "memory");
        }
        __syncthreads();
        uint32_t sA = sbase + (it & 1) * 2 * STAGE_BYTES;
        uint32_t sB = sA + STAGE_BYTES;
#pragma unroll
        for (int ks = 0; ks < 2; ks++) {
            int kbyte = ks * 32;
            uint32_t a[4][4], b[2][4];
#pragma unroll
            for (int i = 0; i < 4; i++) {
                uint32_t addr = sA + (wm * 64 + i * 16 + lrow) * PITCH + kbyte + lcol;
                asm volatile("ldmatrix.sync.aligned.m8n8.x4.shared.b16 {%0,%1,%2,%3}, [%4];"
                             : "=r"(a[i][0]), "=r"(a[i][1]), "=r"(a[i][2]), "=r"(a[i][3]) : "r"(addr));
            }
#pragma unroll
            for (int p = 0; p < 2; p++) {
                uint32_t addr = sB + (wn * 32 + p * 16 + lrow) * PITCH + kbyte + lcol;
                asm volatile("ldmatrix.sync.aligned.m8n8.x4.shared.b16 {%0,%1,%2,%3}, [%4];"
                             : "=r"(b[p][0]), "=r"(b[p][1]), "=r"(b[p][2]), "=r"(b[p][3]) : "r"(addr));
            }
#pragma unroll
            for (int i = 0; i < 4; i++)
#pragma unroll
                for (int j = 0; j < 4; j++) {
                    uint32_t b0 = b[j >> 1][j & 1];
                    uint32_t b1 = b[j >> 1][2 + (j & 1)];
                    asm volatile(
                        "mma.sync.aligned.m16n8k16.row.col.f32.f16.f16.f32 "
                        "{%0,%1,%2,%3}, {%4,%5,%6,%7}, {%8,%9}, {%0,%1,%2,%3};"
                        : "+f"(acc[i][j][0]), "+f"(acc[i][j][1]), "+f"(acc[i][j][2]), "+f"(acc[i][j][3])
                        : "r"(a[i][0]), "r"(a[i][1]), "r"(a[i][2]), "r"(a[i][3]),
                          "r"(b0), "r"(b1));
                }
        }
        __syncthreads();
    }
#pragma unroll
    for (int i = 0; i < 4; i++) {
        int r0 = rowBase + wm * 64 + i * 16 + g;
#pragma unroll
        for (int j = 0; j < 4; j++) {
            int c0 = colBase + wn * 32 + j * 8 + tg * 2;
            if (r0 < Nrows) {
                if (c0     < Nout) C[(size_t)r0 * ldc + c0]     = acc[i][j][0];
                if (c0 + 1 < Nout) C[(size_t)r0 * ldc + c0 + 1] = acc[i][j][1];
            }
            if (r0 + 8 < Nrows) {
                if (c0     < Nout) C[(size_t)(r0 + 8) * ldc + c0]     = acc[i][j][2];
                if (c0 + 1 < Nout) C[(size_t)(r0 + 8) * ldc + c0 + 1] = acc[i][j][3];
            }
        }
    }
}

// ---------------- CSR construction ----------------
__global__ void zero_i(int* p, int n) {
    int i = blockIdx.x * blockDim.x + threadIdx.x;
    if (i < n) p[i] = 0;
}
__global__ void hist_dst(const int* __restrict__ ei, int* __restrict__ deg) {
    int e = blockIdx.x * blockDim.x + threadIdx.x;
    if (e < EE) atomicAdd(&deg[ei[EE + e]], 1);
}
__global__ void scan_deg(const int* __restrict__ deg, int* __restrict__ rowptr, int* __restrict__ cursor) {
    __shared__ int part[512];
    int t = threadIdx.x;
    const int CH = (NN + 511) / 512;
    int start = t * CH;
    int s = 0;
    for (int i = 0; i < CH; i++) {
        int idx = start + i;
        if (idx < NN) s += deg[idx];
    }
    part[t] = s;
    __syncthreads();
    for (int off = 1; off < 512; off <<= 1) {
        int v = (t >= off) ? part[t - off] : 0;
        __syncthreads();
        part[t] += v;
        __syncthreads();
    }
    int base = (t == 0) ? 0 : part[t - 1];
    for (int i = 0; i < CH; i++) {
        int idx = start + i;
        if (idx < NN) {
            rowptr[idx] = base;
            cursor[idx] = base;
            base += deg[idx];
        }
    }
    if (t == 511) rowptr[NN] = part[511];
}
__global__ void scatter_csr(const int* __restrict__ ei, int* __restrict__ cursor,
                            int* __restrict__ csrsrc) {
    int e = blockIdx.x * blockDim.x + threadIdx.x;
    if (e >= EE) return;
    int dst = ei[EE + e];
    int p = atomicAdd(&cursor[dst], 1);
    csrsrc[p] = ei[e];
}

// ---------------- softmax: standalone kernel, online max+den (2 passes) ----------------
__global__ void softmax_csr(const int* __restrict__ rowptr, const int* __restrict__ csrsrc,
                            const float* __restrict__ AS, const float* __restrict__ AD,
                            int pitch, float* __restrict__ alpha) {
    int w    = (blockIdx.x * blockDim.x + threadIdx.x) >> 5;
    int lane = threadIdx.x & 31;
    if (w >= NN) return;
    int h  = lane >> 3;
    int j0 = lane & 7;
    int beg = rowptr[w], end = rowptr[w + 1];
    float adv = AD[(size_t)w * pitch + h];
    float m = -INFINITY, den = 0.f;
    for (int i = beg + j0; i < end; i += 8) {
        float lg = AS[(size_t)csrsrc[i] * pitch + h] + adv;
        lg = lg > 0.f ? lg : 0.2f * lg;
        alpha[(size_t)i * HEADS + h] = lg;
        if (lg > m) { den = den * expf(m - lg) + 1.f; m = lg; }
        else        { den += expf(lg - m); }
    }
#pragma unroll
    for (int o = 1; o < 8; o <<= 1) {
        float mo = __shfl_xor_sync(0xffffffffu, m, o);
        float dn = __shfl_xor_sync(0xffffffffu, den, o);
        float mn = fmaxf(m, mo);
        float f1 = (m  == mn) ? 1.f : expf(m - mn);
        float f2 = (mo == mn) ? 1.f : expf(mo - mn);
        den = den * f1 + dn * f2;
        m = mn;
    }
    float inv = 1.f / (den + 1e-16f);
    for (int i = beg + j0; i < end; i += 8)
        alpha[(size_t)i * HEADS + h] = expf(alpha[(size_t)i * HEADS + h] - m) * inv;
}

// ---------------- float4 aggregation, unroll-8/4/scalar ----------------
__device__ __forceinline__ float4 agg_acc4(const int* __restrict__ rowptr,
                                           const int* __restrict__ csrsrc,
                                           const float* __restrict__ alpha,
                                           const float* __restrict__ xh,
                                           int pitch, int n, int cb, int h) {
    int beg = rowptr[n], end = rowptr[n + 1];
    float4 acc = make_float4(0.f, 0.f, 0.f, 0.f);
    int i = beg;
    for (; i + 7 < end; i += 8) {
        int s[8]; float a[8]; float4 x[8];
#pragma unroll
        for (int u = 0; u < 8; u++) s[u] = csrsrc[i + u];
#pragma unroll
        for (int u = 0; u < 8; u++) a[u] = alpha[(size_t)(i + u) * HEADS + h];
#pragma unroll
        for (int u = 0; u < 8; u++) x[u] = *(const float4*)(xh + (size_t)s[u] * pitch + cb);
#pragma unroll
        for (int u = 0; u < 8; u++) {
            acc.x += a[u] * x[u].x; acc.y += a[u] * x[u].y;
            acc.z += a[u] * x[u].z; acc.w += a[u] * x[u].w;
        }
    }
    for (; i + 3 < end; i += 4) {
        int s0 = csrsrc[i], s1 = csrsrc[i + 1], s2 = csrsrc[i + 2], s3 = csrsrc[i + 3];
        float a0 = alpha[(size_t)i * HEADS + h];
        float a1 = alpha[(size_t)(i + 1) * HEADS + h];
        float a2 = alpha[(size_t)(i + 2) * HEADS + h];
        float a3 = alpha[(size_t)(i + 3) * HEADS + h];
        float4 x0 = *(const float4*)(xh + (size_t)s0 * pitch + cb);
        float4 x1 = *(const float4*)(xh + (size_t)s1 * pitch + cb);
        float4 x2 = *(const float4*)(xh + (size_t)s2 * pitch + cb);
        float4 x3 = *(const float4*)(xh + (size_t)s3 * pitch + cb);
        acc.x += a0 * x0.x + a1 * x1.x + a2 * x2.x + a3 * x3.x;
        acc.y += a0 * x0.y + a1 * x1.y + a2 * x2.y + a3 * x3.y;
        acc.z += a0 * x0.z + a1 * x1.z + a2 * x2.z + a3 * x3.z;
        acc.w += a0 * x0.w + a1 * x1.w + a2 * x2.w + a3 * x3.w;
    }
    for (; i < end; i++) {
        float a = alpha[(size_t)i * HEADS + h];
        float4 x = *(const float4*)(xh + (size_t)csrsrc[i] * pitch + cb);
        acc.x += a * x.x; acc.y += a * x.y; acc.z += a * x.z; acc.w += a * x.w;
    }
    return acc;
}
__device__ __forceinline__ float4 agg_acc4_mh(const int* __restrict__ rowptr,
                                              const int* __restrict__ csrsrc,
                                              const float* __restrict__ alpha,
                                              const float* __restrict__ xh,
                                              int pitch, int n, int cb,
                                              int h0, int h1, int h2, int h3) {
    int beg = rowptr[n], end = rowptr[n + 1];
    float4 acc = make_float4(0.f, 0.f, 0.f, 0.f);
    for (int i = beg; i < end; i++) {
        float4 av = *(const float4*)(alpha + (size_t)i * HEADS);
        const float* ap = (const float*)&av;
        float4 x = *(const float4*)(xh + (size_t)csrsrc[i] * pitch + cb);
        acc.x += ap[h0] * x.x; acc.y += ap[h1] * x.y;
        acc.z += ap[h2] * x.z; acc.w += ap[h3] * x.w;
    }
    return acc;
}

__global__ __launch_bounds__(64) void agg_final1(
        const int* __restrict__ rowptr, const int* __restrict__ csrsrc,
        const float* __restrict__ alpha, const float* __restrict__ xh,
        const float* __restrict__ b1, const float* __restrict__ lin1b,
        float* __restrict__ h_out, __half* __restrict__ Ap) {
    int n = blockIdx.x, c4 = threadIdx.x;
    int cb = c4 * 4;
    float4 acc = agg_acc4(rowptr, csrsrc, alpha, xh, P1, n, cb, cb >> 6);
    float4 skip = *(const float4*)(xh + (size_t)n * P1 + 256 + cb);
    float4 bb   = *(const float4*)(b1 + cb);
    float4 lb   = *(const float4*)(lin1b + cb);
    float v[4] = { acc.x + bb.x + skip.x + lb.x, acc.y + bb.y + skip.y + lb.y,
                   acc.z + bb.z + skip.z + lb.z, acc.w + bb.w + skip.w + lb.w };
    __half* row = Ap + (size_t)n * 256;
    float* ho = h_out + (size_t)n * M1 + cb;
#pragma unroll
    for (int u = 0; u < 4; u++) {
        float t = v[u] > 0.f ? v[u] : expm1f(v[u]);
        ho[u] = t;
        row[cb + u] = __float2half_rn(t);
    }
}

__global__ __launch_bounds__(64) void agg_final2(
        const int* __restrict__ rowptr, const int* __restrict__ csrsrc,
        const float* __restrict__ alpha, const float* __restrict__ xh,
        const float* __restrict__ b2,
        float* __restrict__ h_io, __half* __restrict__ Ap) {
    int n = blockIdx.x, c4 = threadIdx.x;
    int cb = c4 * 4;
    float4 acc = agg_acc4(rowptr, csrsrc, alpha, xh, P2, n, cb, cb >> 6);
    float4 bb = *(const float4*)(b2 + cb);
    float* hp = h_io + (size_t)n * M1 + cb;
    float4 hv = *(const float4*)hp;
    float v[4] = { acc.x + bb.x + hv.x, acc.y + bb.y + hv.y,
                   acc.z + bb.z + hv.z, acc.w + bb.w + hv.w };
    __half* row = Ap + (size_t)n * 256;
#pragma unroll
    for (int u = 0; u < 4; u++) {
        float t = v[u] > 0.f ? v[u] : expm1f(v[u]);
        hp[u] = t;
        row[cb + u] = __float2half_rn(t);
    }
}

__global__ __launch_bounds__(128) void agg_final3(
        const int* __restrict__ rowptr, const int* __restrict__ csrsrc,
        const float* __restrict__ alpha, const float* __restrict__ xh,
        const float* __restrict__ b3, const float* __restrict__ lin3b,
        float* __restrict__ out) {
    __shared__ float sm[M3];
    int n = blockIdx.x, c4 = threadIdx.x;
    if (c4 < 121) {
        int cb = c4 * 4;
        int h0 = cb / NCLS, h1 = (cb + 1) / NCLS, h2 = (cb + 2) / NCLS, h3 = (cb + 3) / NCLS;
        float4 acc;
        if (h0 == h3) acc = agg_acc4(rowptr, csrsrc, alpha, xh, P3, n, cb, h0);
        else          acc = agg_acc4_mh(rowptr, csrsrc, alpha, xh, P3, n, cb, h0, h1, h2, h3);
        sm[cb] = acc.x; sm[cb + 1] = acc.y; sm[cb + 2] = acc.z; sm[cb + 3] = acc.w;
    }
    __syncthreads();
    int c = threadIdx.x;
    if (c < NCLS) {
        float s = 0.25f * (sm[c] + sm[NCLS + c] + sm[2 * NCLS + c] + sm[3 * NCLS + c]);
        out[(size_t)n * NCLS + c] = s + b3[c] + xh[(size_t)n * P3 + 484 + c] + lin3b[c];
    }
}

// ---------------- host ----------------
static void launch_gemm(const __half* Ap, const __half* Bp, float* C,
                        int Nrows, int Kp, int Nout, int ldc) {
    dim3 gg((Nout + 127) / 128, (Nrows + 127) / 128);
    gemm_mma<<<gg, 256>>>(Ap, Bp, C, Nrows, Kp, Nout, ldc);
}

extern "C" void kernel_launch(void* const* d_in, const int* in_sizes, int n_in,
                              void* d_out, int out_size) {
    const float* x      = (const float*)d_in[0];
    const int*   ei     = (const int*)  d_in[1];
    const float* W1     = (const float*)d_in[2];
    const float* a1s    = (const float*)d_in[3];
    const float* a1d    = (const float*)d_in[4];
    const float* b1     = (const float*)d_in[5];
    const float* lin1W  = (const float*)d_in[6];
    const float* lin1b  = (const float*)d_in[7];
    const float* W2     = (const float*)d_in[8];
    const float* a2s    = (const float*)d_in[9];
    const float* a2d    = (const float*)d_in[10];
    const float* b2     = (const float*)d_in[11];
    const float* W3     = (const float*)d_in[12];
    const float* a3s    = (const float*)d_in[13];
    const float* a3d    = (const float*)d_in[14];
    const float* b3     = (const float*)d_in[15];
    const float* lin3W  = (const float*)d_in[16];
    const float* lin3b  = (const float*)d_in[17];
    float* out = (float*)d_out;

    float *xh, *h, *alpha, *wext;
    __half *Ah, *Bt;
    int *deg, *rowptr, *cursor, *csrsrc;
    cudaGetSymbolAddress((void**)&xh,  g_xh);
    cudaGetSymbolAddress((void**)&h,   g_h);
    cudaGetSymbolAddress((void**)&alpha, g_alpha);
    cudaGetSymbolAddress((void**)&wext, g_wext);
    cudaGetSymbolAddress((void**)&Ah,  g_Ah);
    cudaGetSymbolAddress((void**)&Bt,  g_Bt);
    cudaGetSymbolAddress((void**)&deg,    g_deg);
    cudaGetSymbolAddress((void**)&rowptr, g_rowptr);
    cudaGetSymbolAddress((void**)&cursor, g_cursor);
    cudaGetSymbolAddress((void**)&csrsrc, g_csrsrc);

    // ---- all weight prep + input conversion up front ----
    convA<<<2048, 256>>>(x, Ah, NN, FIN);
    wext_all<<<(5120 + 255) / 256, 256>>>(W1, a1s, a1d, W2, a2s, a2d, W3, a3s, a3d, wext);
    convB_L1<<<(520 * 128 + 255) / 256, 256>>>(W1, lin1W, wext, Bt + BT_L1);
    convB_W2<<<(264 * 256 + 255) / 256, 256>>>(W2, wext + 2048, Bt + BT_L2);
    convB_L3<<<(640 * 256 + 255) / 256, 256>>>(W3, lin3W, wext + 4096, Bt + BT_L3);

    // ---- CSR build ----
    zero_i<<<(NN + 255) / 256, 256>>>(deg, NN);
    hist_dst<<<(EE + 255) / 256, 256>>>(ei, deg);
    scan_deg<<<1, 512>>>(deg, rowptr, cursor);
    scatter_csr<<<(EE + 255) / 256, 256>>>(ei, cursor, csrsrc);

    // ---- layer 1 ----
    launch_gemm(Ah, Bt + BT_L1, xh, NN, 128, 520, P1);
    softmax_csr<<<(NN * 32 + 255) / 256, 256>>>(rowptr, csrsrc, xh + 512, xh + 516, P1, alpha);
    agg_final1<<<NN, 64>>>(rowptr, csrsrc, alpha, xh, b1, lin1b, h, Ah);

    // ---- layer 2 ----
    launch_gemm(Ah, Bt + BT_L2, xh, NN, 256, 264, P2);
    softmax_csr<<<(NN * 32 + 255) / 256, 256>>>(rowptr, csrsrc, xh + 256, xh + 260, P2, alpha);
    agg_final2<<<NN, 64>>>(rowptr, csrsrc, alpha, xh, b2, h, Ah);

    // ---- layer 3 ----
    launch_gemm(Ah, Bt + BT_L3, xh, NN, 256, 613, P3);
    softmax_csr<<<(NN * 32 + 255) / 256, 256>>>(rowptr, csrsrc, xh + 605, xh + 609, P3, alpha);
    agg_final3<<<NN, 128>>>(rowptr, csrsrc, alpha, xh, b3, lin3b, out);

    (void)in_sizes; (void)n_in; (void)out_size;
}